// round 13
// baseline (speedup 1.0000x reference)
#include <cuda_runtime.h>
#include <cstdint>
#include <cstddef>

typedef unsigned long long ull;

#define TS 2048
#define Y1_ELEMS ((size_t)TS * 64 * 256)

// scratch (allocation-free rule)
__device__ float g_gx[(size_t)TS * 64 * 1024];
__device__ float g_y0[(size_t)TS * 64 * 256];
// h exchange through L2: [buf][group][k][batch]
__device__ float g_hx[2][16][256][4];
// per-layer, per-group, PER-RANK monotonic flags (each on own 128B line)
__device__ __align__(128) unsigned g_flag[2][16][8][32];
__device__ __align__(128) unsigned g_fin[2][16][32];

__device__ __forceinline__ ull fma2(ull a, ull b, ull c) {
    ull d; asm("fma.rn.f32x2 %0,%1,%2,%3;" : "=l"(d) : "l"(a), "l"(b), "l"(c)); return d;
}
__device__ __forceinline__ ull mul2(ull a, ull b) {
    ull d; asm("mul.rn.f32x2 %0,%1,%2;" : "=l"(d) : "l"(a), "l"(b)); return d;
}
__device__ __forceinline__ ull add2(ull a, ull b) {
    ull d; asm("add.rn.f32x2 %0,%1,%2;" : "=l"(d) : "l"(a), "l"(b)); return d;
}
__device__ __forceinline__ ull pk(float lo, float hi) {
    ull r; asm("mov.b64 %0,{%1,%2};" : "=l"(r) : "f"(lo), "f"(hi)); return r;
}
__device__ __forceinline__ void upk(ull a, float& x, float& y) {
    asm("mov.b64 {%0,%1},%2;" : "=f"(x), "=f"(y) : "l"(a));
}
__device__ __forceinline__ ull dup2(float x) {
    ull r; asm("mov.b64 %0,{%1,%1};" : "=l"(r) : "f"(x)); return r;
}
__device__ __forceinline__ float ex2f(float x) {
    float r; asm("ex2.approx.f32 %0,%1;" : "=f"(r) : "f"(x)); return r;
}
__device__ __forceinline__ float rcpf(float x) {
    float r; asm("rcp.approx.f32 %0,%1;" : "=f"(r) : "f"(x)); return r;
}
__device__ __forceinline__ float sigf(float x) {
    return rcpf(1.f + ex2f(-1.44269504f * x));
}
__device__ __forceinline__ float tanhap(float x) {
    float r; asm("tanh.approx.f32 %0,%1;" : "=f"(r) : "f"(x)); return r;
}
__device__ __forceinline__ unsigned ldacq(const unsigned* p) {
    unsigned v;
    asm volatile("ld.acquire.gpu.global.u32 %0,[%1];" : "=r"(v) : "l"(p) : "memory");
    return v;
}

// ---------------------------------------------------------------------------
// GEMM: g_gx[m][n] = A_row(m) . W[:,n] + bias[n],  M = TS*64, N = 1024
// mode 0: A_row(m) = x + ((m&63)*TS + (m>>6))*128, K=128
// mode 1: A_row(m) = g_y0 + m*256,                 K=256
// ---------------------------------------------------------------------------
__global__ void __launch_bounds__(256, 1)
gemm_k(const float* __restrict__ A, const float* __restrict__ W,
       const float* __restrict__ bias, int K, int mode)
{
    __shared__ float As[16][132];
    __shared__ float Bs[16][128];

    const int tid = threadIdx.x;
    const int n0 = blockIdx.x * 128;
    const int m0 = blockIdx.y * 128;

    const int ar = tid >> 1;
    const int ac = (tid & 1) * 8;
    const int m = m0 + ar;
    const float* arow = mode ? (g_y0 + (size_t)m * 256)
                             : (A + ((size_t)(m & 63) * TS + (m >> 6)) * 128);
    const float* wp = W + (size_t)(tid >> 4) * 1024 + n0 + (tid & 15) * 8;

    const int tm = tid >> 4, tn = tid & 15;

    ull acc[8][4];
#pragma unroll
    for (int i = 0; i < 8; ++i)
#pragma unroll
        for (int j = 0; j < 4; ++j) acc[i][j] = 0ull;

#pragma unroll 1
    for (int k0 = 0; k0 < K; k0 += 16) {
        float4 a0 = *(const float4*)(arow + k0 + ac);
        float4 a1 = *(const float4*)(arow + k0 + ac + 4);
        float4 w0 = *(const float4*)(wp + (size_t)k0 * 1024);
        float4 w1 = *(const float4*)(wp + (size_t)k0 * 1024 + 4);
        __syncthreads();
        As[ac + 0][ar] = a0.x; As[ac + 1][ar] = a0.y;
        As[ac + 2][ar] = a0.z; As[ac + 3][ar] = a0.w;
        As[ac + 4][ar] = a1.x; As[ac + 5][ar] = a1.y;
        As[ac + 6][ar] = a1.z; As[ac + 7][ar] = a1.w;
        *(float4*)&Bs[tid >> 4][(tid & 15) * 8] = w0;
        *(float4*)&Bs[tid >> 4][(tid & 15) * 8 + 4] = w1;
        __syncthreads();
#pragma unroll
        for (int kk = 0; kk < 16; ++kk) {
            float4 av0 = *(const float4*)&As[kk][tm * 8];
            float4 av1 = *(const float4*)&As[kk][tm * 8 + 4];
            float av[8] = {av0.x, av0.y, av0.z, av0.w, av1.x, av1.y, av1.z, av1.w};
            const ull* bp = (const ull*)&Bs[kk][0];
            ull bv[4];
#pragma unroll
            for (int c = 0; c < 4; ++c) bv[c] = bp[tn * 4 + c];
#pragma unroll
            for (int r = 0; r < 8; ++r) {
                ull a2 = dup2(av[r]);
#pragma unroll
                for (int c = 0; c < 4; ++c) acc[r][c] = fma2(a2, bv[c], acc[r][c]);
            }
        }
    }

    float bb[8];
#pragma unroll
    for (int c = 0; c < 8; ++c) bb[c] = bias[n0 + tn * 8 + c];

#pragma unroll
    for (int r = 0; r < 8; ++r) {
        float v[8];
#pragma unroll
        for (int c = 0; c < 4; ++c) upk(acc[r][c], v[2 * c], v[2 * c + 1]);
#pragma unroll
        for (int c = 0; c < 8; ++c) v[c] += bb[c];
        float* op = g_gx + (size_t)(m0 + tm * 8 + r) * 1024 + n0 + tn * 8;
        *(float4*)op = make_float4(v[0], v[1], v[2], v[3]);
        *(float4*)(op + 4) = make_float4(v[4], v[5], v[6], v[7]);
    }
}

// ---------------------------------------------------------------------------
// Recurrence (R12 base + rank-staggered pipelined matvec):
// 128 CTAs; group g = blockIdx>>3 (8 CTAs), rank r = blockIdx&7.
// Group handles batches [g*4, g*4+4). Rank owns units [r*32, r*32+32).
// Warp w owns 4 units x 4 gates x 4 batches. Chunk i = source rank (r+i)&7.
//  - chunk 0 (own rank) is read from smem staging hsm -> starts with ZERO
//    wait after the producer bar; no L2 read for own data.
//  - chunks 1..7: software-pipelined — flag for chunk i+1 acquire-loaded one
//    fma-block early, h4 ldcg for chunk i+1 issued one block early; chunk i's
//    fma block covers both latencies. L2 round trip overlaps compute, and
//    per-rank skew is absorbed instead of maxed.
// ---------------------------------------------------------------------------
__global__ void __launch_bounds__(256, 1)
recur_k(const float* __restrict__ whh, float* __restrict__ out, int layer)
{
    __shared__ float gxs[2][4][32][4];   // [buf][batch][unit_local][gate]
    __shared__ float ysm[4][33];         // [batch][unit_local] (padded)
    __shared__ __align__(16) float hsm[2][32][4];  // own-rank h staging

    const int tid  = threadIdx.x;
    const int w    = tid >> 5;
    const int lane = tid & 31;
    const int grp  = blockIdx.x >> 3;
    const int r    = blockIdx.x & 7;
    const int gb0  = grp * 4;

    // epilogue identity
    const int cp = lane >> 2;          // col-pair 0..7
    const int b  = lane & 3;           // batch 0..3
    const int gp = cp & 1;             // 0 -> (f,i), 1 -> (o,g)
    const int u  = cp >> 1;            // unit-local in warp 0..3
    const int jj = r * 32 + w * 4 + u;

    // gx loader identity: 2 consecutive floats per thread
    const int b2    = tid >> 6;        // batch 0..3
    const int gate2 = (tid >> 4) & 3;  // gate 0..3
    const int u2    = tid & 15;        // unit pair 0..15
    const size_t gx_off = (size_t)(gb0 + b2) * 1024 + gate2 * 256 + r * 32 + 2 * u2;

    // weights: wreg[i][cp] for k = ((r+i)&7)*32 + lane, cols (cA, cA+256)
    ull wreg[8][8];
#pragma unroll
    for (int i = 0; i < 8; ++i) {
        const int k = (((r + i) & 7) * 32) + lane;
#pragma unroll
        for (int cpi = 0; cpi < 8; ++cpi) {
            const int cA = (2 * (cpi & 1)) * 256 + r * 32 + w * 4 + (cpi >> 1);
            const float* wp = whh + (size_t)k * 1024 + cA;
            wreg[i][cpi] = pk(wp[0], wp[256]);
        }
    }

    unsigned* myflag = &g_flag[layer][grp][r][0];
    unsigned* fin    = &g_fin[layer][grp][0];

    float cst = 0.f;
    float* yout = layer ? out : g_y0;
    float* hn = out + Y1_ELEMS + (size_t)layer * 16384;
    float* cn = out + Y1_ELEMS + 32768 + (size_t)layer * 16384;

    // preload step-0 gx; zero hsm
    {
        float2 g0 = __ldg((const float2*)(g_gx + (size_t)(TS - 1) * 64 * 1024 + gx_off));
        gxs[0][b2][2 * u2][gate2]     = g0.x;
        gxs[0][b2][2 * u2 + 1][gate2] = g0.y;
        ((float*)hsm)[tid] = 0.f;     // 256 floats = 2*32*4
    }
    __syncthreads();

#pragma unroll 1
    for (int s = 0; s < TS; ++s) {
        const int cur = s & 1;
        const int nxt = cur ^ 1;

        // coalesced prefetch of next step's gx (consumed next iteration)
        float2 gld = make_float2(0.f, 0.f);
        if (s + 1 < TS)
            gld = __ldg((const float2*)(g_gx + (size_t)(TS - 2 - s) * 64 * 1024 + gx_off));

        // early flag preload for chunk 1
        unsigned fv = 0xffffffffu;
        if (s) fv = ldacq(&g_flag[layer][grp][(r + 1) & 7][0]);

        ull v[32];
        // chunk 0: own rank from smem — zero wait
        {
            float4 h4 = *(const float4*)&hsm[cur][lane][0];
            ull hd0 = dup2(h4.x), hd1 = dup2(h4.y), hd2 = dup2(h4.z), hd3 = dup2(h4.w);
#pragma unroll
            for (int cpi = 0; cpi < 8; ++cpi) {
                v[cpi * 4 + 0] = mul2(hd0, wreg[0][cpi]);
                v[cpi * 4 + 1] = mul2(hd1, wreg[0][cpi]);
                v[cpi * 4 + 2] = mul2(hd2, wreg[0][cpi]);
                v[cpi * 4 + 3] = mul2(hd3, wreg[0][cpi]);
            }
        }

        // prime pipeline: confirm flag 1, issue h-load 1, preload flag 2
        float4 h4buf = make_float4(0.f, 0.f, 0.f, 0.f);
        if (s) {
            if (fv < (unsigned)s) {
                const unsigned* fp = &g_flag[layer][grp][(r + 1) & 7][0];
#pragma unroll 1
                while (ldacq(fp) < (unsigned)s) { }
            }
            h4buf = __ldcg((const float4*)&g_hx[cur][grp][((r + 1) & 7) * 32 + lane][0]);
            fv = ldacq(&g_flag[layer][grp][(r + 2) & 7][0]);
        }

#pragma unroll
        for (int i = 1; i < 8; ++i) {
            float4 h4 = h4buf;
            if (i < 7 && s) {
                const int rn = (r + i + 1) & 7;
                if (fv < (unsigned)s) {
                    const unsigned* fp = &g_flag[layer][grp][rn][0];
#pragma unroll 1
                    while (ldacq(fp) < (unsigned)s) { }
                }
                h4buf = __ldcg((const float4*)&g_hx[cur][grp][rn * 32 + lane][0]);
                if (i < 6) fv = ldacq(&g_flag[layer][grp][(r + i + 2) & 7][0]);
            }
            ull hd0 = dup2(h4.x), hd1 = dup2(h4.y), hd2 = dup2(h4.z), hd3 = dup2(h4.w);
#pragma unroll
            for (int cpi = 0; cpi < 8; ++cpi) {
                v[cpi * 4 + 0] = fma2(hd0, wreg[i][cpi], v[cpi * 4 + 0]);
                v[cpi * 4 + 1] = fma2(hd1, wreg[i][cpi], v[cpi * 4 + 1]);
                v[cpi * 4 + 2] = fma2(hd2, wreg[i][cpi], v[cpi * 4 + 2]);
                v[cpi * 4 + 3] = fma2(hd3, wreg[i][cpi], v[cpi * 4 + 3]);
            }
        }

        // reduce-scatter butterfly: lane l ends holding (cp=l>>2, b=l&3)
#pragma unroll
        for (int t = 0; t < 5; ++t) {
            const int mybit = (lane >> t) & 1;
            const int n = 32 >> t;
#pragma unroll
            for (int i = 0; i < 16; ++i) {
                if (i < (n >> 1)) {
                    ull lo = v[2 * i], hi = v[2 * i + 1];
                    ull send = mybit ? lo : hi;
                    ull recv = __shfl_xor_sync(0xffffffffu, send, 1 << t);
                    v[i] = add2(mybit ? hi : lo, recv);
                }
            }
        }

        // stage next step's gx into the other smem buffer
        if (s + 1 < TS) {
            gxs[nxt][b2][2 * u2][gate2]     = gld.x;
            gxs[nxt][b2][2 * u2 + 1][gate2] = gld.y;
        }

        // epilogue: compute h; stage own h (hsm) + publish remote h (L2)
        float h1 = 0.f;
        {
            float2 gx2 = *(const float2*)&gxs[cur][b][w * 4 + u][2 * gp];
            float p0, p1; upk(v[0], p0, p1);
            p0 += gx2.x; p1 += gx2.y;
            float a0 = sigf(p0);
            float a1 = gp ? tanhap(p1) : sigf(p1);
            ull other = __shfl_xor_sync(0xffffffffu, pk(a0, a1), 4);
            if (gp == 0) {
                float so, tg; upk(other, so, tg);
                cst = a0 * cst + a1 * tg;
                h1 = so * tanhap(cst);
                if (s < TS - 1) {
                    g_hx[nxt][grp][jj][b] = h1;
                    hsm[nxt][w * 4 + u][b] = h1;
                }
                ysm[b][w * 4 + u] = h1;
            }
        }

        __syncthreads();              // h + staging stores happen-before release
        if (s < TS - 1 && tid == 0)
            asm volatile("st.release.gpu.global.u32 [%0], %1;"
                         :: "l"(myflag), "r"((unsigned)(s + 1)) : "memory");

        // coalesced outputs — off the critical chain
        if (w < 4)
            yout[((size_t)s * 64 + gb0 + w) * 256 + r * 32 + lane] = ysm[w][lane];
        if (s == TS - 1 && gp == 0) {
            size_t hi_ = (size_t)(gb0 + b) * 256 + jj;
            hn[hi_] = h1; cn[hi_] = cst;
        }
    }

    // reset flags for the next graph replay (deterministic launches)
    __syncthreads();
    if (tid == 0) {
        asm volatile("red.release.gpu.global.add.u32 [%0], 1;" :: "l"(fin) : "memory");
        if (r == 0) {
#pragma unroll 1
            while (ldacq(fin) < 8u) { }
#pragma unroll
            for (int d = 0; d < 8; ++d)
                asm volatile("st.global.u32 [%0], %1;"
                             :: "l"(&g_flag[layer][grp][d][0]), "r"(0u) : "memory");
            asm volatile("st.global.u32 [%0], %1;" :: "l"(fin), "r"(0u) : "memory");
        }
    }
}

extern "C" void kernel_launch(void* const* d_in, const int* in_sizes, int n_in,
                              void* d_out, int out_size)
{
    const float* x    = (const float*)d_in[0];
    const float* wih0 = (const float*)d_in[1];
    const float* whh0 = (const float*)d_in[2];
    const float* b0   = (const float*)d_in[3];
    const float* wih1 = (const float*)d_in[4];
    const float* whh1 = (const float*)d_in[5];
    const float* b1   = (const float*)d_in[6];
    float* out = (float*)d_out;

    dim3 gg(8, 1024);
    gemm_k<<<gg, 256>>>(x, wih0, b0, 128, 0);
    recur_k<<<128, 256>>>(whh0, out, 0);
    gemm_k<<<gg, 256>>>(x, wih1, b1, 256, 1);
    recur_k<<<128, 256>>>(whh1, out, 1);
}

// round 14
// speedup vs baseline: 1.4797x; 1.4797x over previous
#include <cuda_runtime.h>
#include <cstdint>
#include <cstddef>

typedef unsigned long long ull;

#define TS 2048
#define Y1_ELEMS ((size_t)TS * 64 * 256)

// scratch (allocation-free rule)
__device__ float g_gx[(size_t)TS * 64 * 1024];
__device__ float g_y0[(size_t)TS * 64 * 256];
// h exchange through L2: [buf][group][k][batch]
__device__ float g_hx[2][16][256][4];
// per-layer, per-group, PER-RANK monotonic flags (each on own 128B line)
__device__ __align__(128) unsigned g_flag[2][16][8][32];
__device__ __align__(128) unsigned g_fin[2][16][32];

__device__ __forceinline__ ull fma2(ull a, ull b, ull c) {
    ull d; asm("fma.rn.f32x2 %0,%1,%2,%3;" : "=l"(d) : "l"(a), "l"(b), "l"(c)); return d;
}
__device__ __forceinline__ ull mul2(ull a, ull b) {
    ull d; asm("mul.rn.f32x2 %0,%1,%2;" : "=l"(d) : "l"(a), "l"(b)); return d;
}
__device__ __forceinline__ ull add2(ull a, ull b) {
    ull d; asm("add.rn.f32x2 %0,%1,%2;" : "=l"(d) : "l"(a), "l"(b)); return d;
}
__device__ __forceinline__ ull pk(float lo, float hi) {
    ull r; asm("mov.b64 %0,{%1,%2};" : "=l"(r) : "f"(lo), "f"(hi)); return r;
}
__device__ __forceinline__ void upk(ull a, float& x, float& y) {
    asm("mov.b64 {%0,%1},%2;" : "=f"(x), "=f"(y) : "l"(a));
}
__device__ __forceinline__ ull dup2(float x) {
    ull r; asm("mov.b64 %0,{%1,%1};" : "=l"(r) : "f"(x)); return r;
}
__device__ __forceinline__ float ex2f(float x) {
    float r; asm("ex2.approx.f32 %0,%1;" : "=f"(r) : "f"(x)); return r;
}
__device__ __forceinline__ float rcpf(float x) {
    float r; asm("rcp.approx.f32 %0,%1;" : "=f"(r) : "f"(x)); return r;
}
__device__ __forceinline__ float sigf(float x) {
    return rcpf(1.f + ex2f(-1.44269504f * x));
}
__device__ __forceinline__ float tanhap(float x) {
    float r; asm("tanh.approx.f32 %0,%1;" : "=f"(r) : "f"(x)); return r;
}
__device__ __forceinline__ unsigned ldacq(const unsigned* p) {
    unsigned v;
    asm volatile("ld.acquire.gpu.global.u32 %0,[%1];" : "=r"(v) : "l"(p) : "memory");
    return v;
}
__device__ __forceinline__ unsigned t32(float x) {
    unsigned r; asm("cvt.rna.tf32.f32 %0,%1;" : "=r"(r) : "f"(x)); return r;
}
__device__ __forceinline__ void mma8(float* c, const unsigned* a, const unsigned* b) {
    asm volatile(
        "mma.sync.aligned.m16n8k8.row.col.f32.tf32.tf32.f32 "
        "{%0,%1,%2,%3},{%4,%5,%6,%7},{%8,%9},{%0,%1,%2,%3};"
        : "+f"(c[0]), "+f"(c[1]), "+f"(c[2]), "+f"(c[3])
        : "r"(a[0]), "r"(a[1]), "r"(a[2]), "r"(a[3]), "r"(b[0]), "r"(b[1]));
}

// ---------------------------------------------------------------------------
// tf32 tensor-core GEMM: g_gx[m][n] = A_row(m).W[:,n] + bias[n]
//   M = TS*64, N = 1024.  CTA tile 128x128, k-chunk 32.
//   8 warps: wm = wid&1 (64 rows), wn = wid>>2... wn = wid>>1 (32 cols).
//   Warp tile 64x32 = 4x4 m16n8k8 tiles, acc in fp32 regs.
//   As[m][k] stride 36 and Bs[k][n] stride 136: fragment reads conflict-free.
// mode 0: A_row(m) = x + ((m&63)*TS + (m>>6))*128, K=128
// mode 1: A_row(m) = g_y0 + m*256,                 K=256
// ---------------------------------------------------------------------------
__global__ void __launch_bounds__(256)
gemm_k(const float* __restrict__ A, const float* __restrict__ W,
       const float* __restrict__ bias, int K, int mode)
{
    __shared__ float As[128][36];
    __shared__ float Bs[32][136];

    const int tid  = threadIdx.x;
    const int lane = tid & 31;
    const int wid  = tid >> 5;
    const int wm   = wid & 1;
    const int wn   = wid >> 1;
    const int n0   = blockIdx.x * 128;
    const int m0   = blockIdx.y * 128;

    // A loader: row ar (128 rows, 2 threads/row), 16 floats at ak
    const int ar = tid >> 1, ak = (tid & 1) * 16;
    const int m = m0 + ar;
    const float* arow = mode ? (g_y0 + (size_t)m * 256)
                             : (A + ((size_t)(m & 63) * TS + (m >> 6)) * 128);
    // B loader: row bk (32 rows, 8 threads/row), 16 floats at bn
    const int bk = tid >> 3, bn = (tid & 7) * 16;
    const float* wrow = W + (size_t)bk * 1024 + n0 + bn;

    float acc[16][4];
#pragma unroll
    for (int i = 0; i < 16; ++i)
#pragma unroll
        for (int j = 0; j < 4; ++j) acc[i][j] = 0.f;

    // prefetch chunk 0
    float4 av[4], bv[4];
#pragma unroll
    for (int q = 0; q < 4; ++q) {
        av[q] = *(const float4*)(arow + ak + 4 * q);
        bv[q] = *(const float4*)(wrow + 4 * q);
    }

#pragma unroll 1
    for (int k0 = 0; k0 < K; k0 += 32) {
        __syncthreads();
#pragma unroll
        for (int q = 0; q < 4; ++q) {
            *(float4*)&As[ar][ak + 4 * q] = av[q];
            *(float4*)&Bs[bk][bn + 4 * q] = bv[q];
        }
        __syncthreads();

        if (k0 + 32 < K) {
#pragma unroll
            for (int q = 0; q < 4; ++q) {
                av[q] = *(const float4*)(arow + k0 + 32 + ak + 4 * q);
                bv[q] = *(const float4*)(wrow + (size_t)(k0 + 32) * 1024 + 4 * q);
            }
        }

#pragma unroll
        for (int k8 = 0; k8 < 32; k8 += 8) {
            unsigned af[4][4], bf[4][2];
            const int kk = k8 + (lane & 3);
#pragma unroll
            for (int i = 0; i < 4; ++i) {
                const int row = wm * 64 + i * 16 + (lane >> 2);
                af[i][0] = t32(As[row][kk]);
                af[i][1] = t32(As[row + 8][kk]);
                af[i][2] = t32(As[row][kk + 4]);
                af[i][3] = t32(As[row + 8][kk + 4]);
            }
#pragma unroll
            for (int j = 0; j < 4; ++j) {
                const int col = wn * 32 + j * 8 + (lane >> 2);
                bf[j][0] = t32(Bs[kk][col]);
                bf[j][1] = t32(Bs[kk + 4][col]);
            }
#pragma unroll
            for (int i = 0; i < 4; ++i)
#pragma unroll
                for (int j = 0; j < 4; ++j)
                    mma8(acc[i * 4 + j], af[i], bf[j]);
        }
    }

    // epilogue: add bias, write float2 pairs
#pragma unroll
    for (int j = 0; j < 4; ++j) {
        const int col = n0 + wn * 32 + j * 8 + 2 * (lane & 3);
        float2 bb = *(const float2*)&bias[col];
#pragma unroll
        for (int i = 0; i < 4; ++i) {
            const int row = m0 + wm * 64 + i * 16 + (lane >> 2);
            const float* c = acc[i * 4 + j];
            float2 v0 = make_float2(c[0] + bb.x, c[1] + bb.y);
            float2 v1 = make_float2(c[2] + bb.x, c[3] + bb.y);
            *(float2*)&g_gx[(size_t)row * 1024 + col] = v0;
            *(float2*)&g_gx[(size_t)(row + 8) * 1024 + col] = v1;
        }
    }
}

// ---------------------------------------------------------------------------
// Recurrence: verbatim R10 (best known: 4.88 ms/layer).
// 128 CTAs; group g = blockIdx>>3 (8 CTAs), rank = blockIdx&7.
// Group handles batches [g*4, g*4+4). Rank r owns units [r*32, r*32+32).
// Publish: STG h -> bar.sync -> tid0 st.release.gpu flag[r]=s+1.
// Consume: tids 0..7 poll one flag each -> bar.sync -> 8 back-to-back ldcgs.
// ---------------------------------------------------------------------------
__global__ void __launch_bounds__(256, 1)
recur_k(const float* __restrict__ whh, float* __restrict__ out, int layer)
{
    const int tid  = threadIdx.x;
    const int w    = tid >> 5;
    const int lane = tid & 31;
    const int grp  = blockIdx.x >> 3;
    const int r    = blockIdx.x & 7;
    const int gb0  = grp * 4;

    // epilogue identity
    const int cp = lane >> 2;          // col-pair 0..7
    const int b  = lane & 3;           // batch 0..3
    const int gp = cp & 1;             // 0 -> (f,i), 1 -> (o,g)
    const int u  = cp >> 1;            // unit-local in warp 0..3
    const int jj = r * 32 + w * 4 + u;
    const int colA = (2 * gp) * 256 + jj;

    // weights: wreg[i][cp] for k = i*32 + lane, cols (cA, cA+256)
    ull wreg[8][8];
#pragma unroll
    for (int i = 0; i < 8; ++i) {
        const int k = i * 32 + lane;
#pragma unroll
        for (int cpi = 0; cpi < 8; ++cpi) {
            const int cA = (2 * (cpi & 1)) * 256 + r * 32 + w * 4 + (cpi >> 1);
            const float* wp = whh + (size_t)k * 1024 + cA;
            wreg[i][cpi] = pk(wp[0], wp[256]);
        }
    }

    unsigned* myflag = &g_flag[layer][grp][r][0];
    unsigned* fin    = &g_fin[layer][grp][0];

    float cst = 0.f;
    float* yout = layer ? out : g_y0;
    float* hn = out + Y1_ELEMS + (size_t)layer * 16384;
    float* cn = out + Y1_ELEMS + 32768 + (size_t)layer * 16384;

    // gates_x pipeline
    ull gxr, gxn = 0ull;
    {
        const float* gpx = g_gx + ((size_t)(TS - 1) * 64 + gb0 + b) * 1024 + colA;
        gxr = pk(__ldg(gpx), __ldg(gpx + 256));
    }

#pragma unroll 1
    for (int s = 0; s < TS; ++s) {
        const int cur = s & 1;
        const int nxt = cur ^ 1;

        if (s + 1 < TS) {
            const float* gpx = g_gx + ((size_t)(TS - 2 - s) * 64 + gb0 + b) * 1024 + colA;
            gxn = pk(__ldg(gpx), __ldg(gpx + 256));
        }

        // wait: each of tids 0..7 watches one rank's flag (parallel discovery)
        if (s) {
            if (tid < 8) {
                const unsigned tgt = (unsigned)s;
                const unsigned* fp = &g_flag[layer][grp][tid][0];
#pragma unroll 1
                while (ldacq(fp) < tgt) { }
            }
            __syncthreads();
        }

        // matvec: v[cp*4 + bb]; h read straight from L2 (step 0: h = 0)
        ull v[32];
#pragma unroll
        for (int i = 0; i < 8; ++i) {
            float4 h4 = make_float4(0.f, 0.f, 0.f, 0.f);
            if (s) h4 = __ldcg((const float4*)&g_hx[cur][grp][i * 32 + lane][0]);
            ull hd0 = dup2(h4.x), hd1 = dup2(h4.y), hd2 = dup2(h4.z), hd3 = dup2(h4.w);
            if (i == 0) {
#pragma unroll
                for (int cpi = 0; cpi < 8; ++cpi) {
                    v[cpi * 4 + 0] = mul2(hd0, wreg[0][cpi]);
                    v[cpi * 4 + 1] = mul2(hd1, wreg[0][cpi]);
                    v[cpi * 4 + 2] = mul2(hd2, wreg[0][cpi]);
                    v[cpi * 4 + 3] = mul2(hd3, wreg[0][cpi]);
                }
            } else {
#pragma unroll
                for (int cpi = 0; cpi < 8; ++cpi) {
                    v[cpi * 4 + 0] = fma2(hd0, wreg[i][cpi], v[cpi * 4 + 0]);
                    v[cpi * 4 + 1] = fma2(hd1, wreg[i][cpi], v[cpi * 4 + 1]);
                    v[cpi * 4 + 2] = fma2(hd2, wreg[i][cpi], v[cpi * 4 + 2]);
                    v[cpi * 4 + 3] = fma2(hd3, wreg[i][cpi], v[cpi * 4 + 3]);
                }
            }
        }

        // reduce-scatter butterfly: lane l ends holding (cp=l>>2, b=l&3)
#pragma unroll
        for (int t = 0; t < 5; ++t) {
            const int mybit = (lane >> t) & 1;
            const int n = 32 >> t;
#pragma unroll
            for (int i = 0; i < 16; ++i) {
                if (i < (n >> 1)) {
                    ull lo = v[2 * i], hi = v[2 * i + 1];
                    ull send = mybit ? lo : hi;
                    ull recv = __shfl_xor_sync(0xffffffffu, send, 1 << t);
                    v[i] = add2(mybit ? hi : lo, recv);
                }
            }
        }

        // epilogue: compute h, store ONLY g_hx before the publish
        float h1 = 0.f;
        {
            float p0, p1;
            upk(add2(v[0], gxr), p0, p1);
            float a0 = sigf(p0);
            float a1 = gp ? tanhap(p1) : sigf(p1);
            ull other = __shfl_xor_sync(0xffffffffu, pk(a0, a1), 4);
            if (gp == 0) {
                float so, tg; upk(other, so, tg);
                cst = a0 * cst + a1 * tg;
                h1 = so * tanhap(cst);
                if (s < TS - 1)
                    g_hx[nxt][grp][jj][b] = h1;
            }
        }
        gxr = gxn;

        __syncthreads();              // h stores happen-before the release
        if (s < TS - 1 && tid == 0)
            asm volatile("st.release.gpu.global.u32 [%0], %1;"
                         :: "l"(myflag), "r"((unsigned)(s + 1)) : "memory");

        // outputs AFTER the publish — off the critical chain
        if (gp == 0) {
            yout[((size_t)s * 64 + gb0 + b) * 256 + jj] = h1;
            if (s == TS - 1) {
                size_t hi_ = (size_t)(gb0 + b) * 256 + jj;
                hn[hi_] = h1; cn[hi_] = cst;
            }
        }
    }

    // reset flags for the next graph replay (deterministic launches)
    __syncthreads();
    if (tid == 0) {
        asm volatile("red.release.gpu.global.add.u32 [%0], 1;" :: "l"(fin) : "memory");
        if (r == 0) {
#pragma unroll 1
            while (ldacq(fin) < 8u) { }
#pragma unroll
            for (int d = 0; d < 8; ++d)
                asm volatile("st.global.u32 [%0], %1;"
                             :: "l"(&g_flag[layer][grp][d][0]), "r"(0u) : "memory");
            asm volatile("st.global.u32 [%0], %1;" :: "l"(fin), "r"(0u) : "memory");
        }
    }
}

extern "C" void kernel_launch(void* const* d_in, const int* in_sizes, int n_in,
                              void* d_out, int out_size)
{
    const float* x    = (const float*)d_in[0];
    const float* wih0 = (const float*)d_in[1];
    const float* whh0 = (const float*)d_in[2];
    const float* b0   = (const float*)d_in[3];
    const float* wih1 = (const float*)d_in[4];
    const float* whh1 = (const float*)d_in[5];
    const float* b1   = (const float*)d_in[6];
    float* out = (float*)d_out;

    dim3 gg(8, 1024);
    gemm_k<<<gg, 256>>>(x, wih0, b0, 128, 0);
    recur_k<<<128, 256>>>(whh0, out, 0);
    gemm_k<<<gg, 256>>>(x, wih1, b1, 256, 1);
    recur_k<<<128, 256>>>(whh1, out, 1);
}

// round 15
// speedup vs baseline: 1.5069x; 1.0184x over previous
#include <cuda_runtime.h>
#include <cstdint>
#include <cstddef>

typedef unsigned long long ull;

#define TS 2048
#define Y1_ELEMS ((size_t)TS * 64 * 256)

// scratch (allocation-free rule)
__device__ float g_gx[(size_t)TS * 64 * 1024];
__device__ float g_y0[(size_t)TS * 64 * 256];
// h exchange through L2: [buf][group][k][batch]
__device__ float g_hx[2][16][256][4];
// per-layer, per-group, PER-RANK monotonic flags (each on own 128B line)
__device__ __align__(128) unsigned g_flag[2][16][8][32];
__device__ __align__(128) unsigned g_fin[2][16][32];

__device__ __forceinline__ ull fma2(ull a, ull b, ull c) {
    ull d; asm("fma.rn.f32x2 %0,%1,%2,%3;" : "=l"(d) : "l"(a), "l"(b), "l"(c)); return d;
}
__device__ __forceinline__ ull mul2(ull a, ull b) {
    ull d; asm("mul.rn.f32x2 %0,%1,%2;" : "=l"(d) : "l"(a), "l"(b)); return d;
}
__device__ __forceinline__ ull add2(ull a, ull b) {
    ull d; asm("add.rn.f32x2 %0,%1,%2;" : "=l"(d) : "l"(a), "l"(b)); return d;
}
__device__ __forceinline__ ull pk(float lo, float hi) {
    ull r; asm("mov.b64 %0,{%1,%2};" : "=l"(r) : "f"(lo), "f"(hi)); return r;
}
__device__ __forceinline__ void upk(ull a, float& x, float& y) {
    asm("mov.b64 {%0,%1},%2;" : "=f"(x), "=f"(y) : "l"(a));
}
__device__ __forceinline__ ull dup2(float x) {
    ull r; asm("mov.b64 %0,{%1,%1};" : "=l"(r) : "f"(x)); return r;
}
__device__ __forceinline__ float ex2f(float x) {
    float r; asm("ex2.approx.f32 %0,%1;" : "=f"(r) : "f"(x)); return r;
}
__device__ __forceinline__ float rcpf(float x) {
    float r; asm("rcp.approx.f32 %0,%1;" : "=f"(r) : "f"(x)); return r;
}
__device__ __forceinline__ float sigf(float x) {
    return rcpf(1.f + ex2f(-1.44269504f * x));
}
__device__ __forceinline__ float tanhap(float x) {
    float r; asm("tanh.approx.f32 %0,%1;" : "=f"(r) : "f"(x)); return r;
}
__device__ __forceinline__ unsigned ldacq(const unsigned* p) {
    unsigned v;
    asm volatile("ld.acquire.gpu.global.u32 %0,[%1];" : "=r"(v) : "l"(p) : "memory");
    return v;
}
__device__ __forceinline__ unsigned t32(float x) {
    unsigned r; asm("cvt.rna.tf32.f32 %0,%1;" : "=r"(r) : "f"(x)); return r;
}
__device__ __forceinline__ void mma8(float* c, const unsigned* a, const unsigned* b) {
    asm volatile(
        "mma.sync.aligned.m16n8k8.row.col.f32.tf32.tf32.f32 "
        "{%0,%1,%2,%3},{%4,%5,%6,%7},{%8,%9},{%0,%1,%2,%3};"
        : "+f"(c[0]), "+f"(c[1]), "+f"(c[2]), "+f"(c[3])
        : "r"(a[0]), "r"(a[1]), "r"(a[2]), "r"(a[3]), "r"(b[0]), "r"(b[1]));
}

// ---------------------------------------------------------------------------
// tf32 tensor-core GEMM (verbatim R14): g_gx[m][n] = A_row(m).W[:,n] + bias[n]
// mode 0: A_row(m) = x + ((m&63)*TS + (m>>6))*128, K=128
// mode 1: A_row(m) = g_y0 + m*256,                 K=256
// ---------------------------------------------------------------------------
__global__ void __launch_bounds__(256)
gemm_k(const float* __restrict__ A, const float* __restrict__ W,
       const float* __restrict__ bias, int K, int mode)
{
    __shared__ float As[128][36];
    __shared__ float Bs[32][136];

    const int tid  = threadIdx.x;
    const int lane = tid & 31;
    const int wid  = tid >> 5;
    const int wm   = wid & 1;
    const int wn   = wid >> 1;
    const int n0   = blockIdx.x * 128;
    const int m0   = blockIdx.y * 128;

    const int ar = tid >> 1, ak = (tid & 1) * 16;
    const int m = m0 + ar;
    const float* arow = mode ? (g_y0 + (size_t)m * 256)
                             : (A + ((size_t)(m & 63) * TS + (m >> 6)) * 128);
    const int bk = tid >> 3, bn = (tid & 7) * 16;
    const float* wrow = W + (size_t)bk * 1024 + n0 + bn;

    float acc[16][4];
#pragma unroll
    for (int i = 0; i < 16; ++i)
#pragma unroll
        for (int j = 0; j < 4; ++j) acc[i][j] = 0.f;

    float4 av[4], bv[4];
#pragma unroll
    for (int q = 0; q < 4; ++q) {
        av[q] = *(const float4*)(arow + ak + 4 * q);
        bv[q] = *(const float4*)(wrow + 4 * q);
    }

#pragma unroll 1
    for (int k0 = 0; k0 < K; k0 += 32) {
        __syncthreads();
#pragma unroll
        for (int q = 0; q < 4; ++q) {
            *(float4*)&As[ar][ak + 4 * q] = av[q];
            *(float4*)&Bs[bk][bn + 4 * q] = bv[q];
        }
        __syncthreads();

        if (k0 + 32 < K) {
#pragma unroll
            for (int q = 0; q < 4; ++q) {
                av[q] = *(const float4*)(arow + k0 + 32 + ak + 4 * q);
                bv[q] = *(const float4*)(wrow + (size_t)(k0 + 32) * 1024 + 4 * q);
            }
        }

#pragma unroll
        for (int k8 = 0; k8 < 32; k8 += 8) {
            unsigned af[4][4], bf[4][2];
            const int kk = k8 + (lane & 3);
#pragma unroll
            for (int i = 0; i < 4; ++i) {
                const int row = wm * 64 + i * 16 + (lane >> 2);
                af[i][0] = t32(As[row][kk]);
                af[i][1] = t32(As[row + 8][kk]);
                af[i][2] = t32(As[row][kk + 4]);
                af[i][3] = t32(As[row + 8][kk + 4]);
            }
#pragma unroll
            for (int j = 0; j < 4; ++j) {
                const int col = wn * 32 + j * 8 + (lane >> 2);
                bf[j][0] = t32(Bs[kk][col]);
                bf[j][1] = t32(Bs[kk + 4][col]);
            }
#pragma unroll
            for (int i = 0; i < 4; ++i)
#pragma unroll
                for (int j = 0; j < 4; ++j)
                    mma8(acc[i * 4 + j], af[i], bf[j]);
        }
    }

#pragma unroll
    for (int j = 0; j < 4; ++j) {
        const int col = n0 + wn * 32 + j * 8 + 2 * (lane & 3);
        float2 bb = *(const float2*)&bias[col];
#pragma unroll
        for (int i = 0; i < 4; ++i) {
            const int row = m0 + wm * 64 + i * 16 + (lane >> 2);
            const float* c = acc[i * 4 + j];
            float2 v0 = make_float2(c[0] + bb.x, c[1] + bb.y);
            float2 v1 = make_float2(c[2] + bb.x, c[3] + bb.y);
            *(float2*)&g_gx[(size_t)row * 1024 + col] = v0;
            *(float2*)&g_gx[(size_t)(row + 8) * 1024 + col] = v1;
        }
    }
}

// ---------------------------------------------------------------------------
// Recurrence (R10 skeleton + three micro-wins):
// 128 CTAs; group g = blockIdx>>3 (8 CTAs), rank r = blockIdx&7.
// Group handles batches [g*4, g*4+4). Rank owns units [r*32, r*32+32).
// Chunk i = source rank (r+i)&7 (rotated weights); chunk 0 = OWN rank,
// read from smem hsm (gated only by the producer bar) and computed BEFORE
// the flag polls. Then one per-warp wait (lanes 0..7 poll the 7 remote
// flags + syncwarp) and 7 back-to-back ldcgs — R10's MLP structure intact.
// h publish: 4 shfls gather each unit's 4 batch values -> 4 STG.128/warp
// (64B contiguous) into g_hx + 1 STS.128 into hsm.
// ---------------------------------------------------------------------------
__global__ void __launch_bounds__(256, 1)
recur_k(const float* __restrict__ whh, float* __restrict__ out, int layer)
{
    __shared__ __align__(16) float hsm[2][32][4];   // own-rank h [buf][ul][b]

    const int tid  = threadIdx.x;
    const int w    = tid >> 5;
    const int lane = tid & 31;
    const int grp  = blockIdx.x >> 3;
    const int r    = blockIdx.x & 7;
    const int gb0  = grp * 4;

    // epilogue identity
    const int cp = lane >> 2;          // col-pair 0..7
    const int b  = lane & 3;           // batch 0..3
    const int gp = cp & 1;             // 0 -> (f,i), 1 -> (o,g)
    const int u  = cp >> 1;            // unit-local in warp 0..3
    const int jj = r * 32 + w * 4 + u;
    const int colA = (2 * gp) * 256 + jj;

    // weights: wreg[i][cp] for k = ((r+i)&7)*32 + lane, cols (cA, cA+256)
    ull wreg[8][8];
#pragma unroll
    for (int i = 0; i < 8; ++i) {
        const int k = ((r + i) & 7) * 32 + lane;
#pragma unroll
        for (int cpi = 0; cpi < 8; ++cpi) {
            const int cA = (2 * (cpi & 1)) * 256 + r * 32 + w * 4 + (cpi >> 1);
            const float* wp = whh + (size_t)k * 1024 + cA;
            wreg[i][cpi] = pk(wp[0], wp[256]);
        }
    }

    unsigned* myflag = &g_flag[layer][grp][r][0];
    unsigned* fin    = &g_fin[layer][grp][0];

    float cst = 0.f;
    float* yout = layer ? out : g_y0;
    float* hn = out + Y1_ELEMS + (size_t)layer * 16384;
    float* cn = out + Y1_ELEMS + 32768 + (size_t)layer * 16384;

    // zero hsm (both buffers); step-0 matvec reads zeros
    ((float*)hsm)[tid] = 0.f;
    __syncthreads();

    // gates_x pipeline
    ull gxr, gxn = 0ull;
    {
        const float* gpx = g_gx + ((size_t)(TS - 1) * 64 + gb0 + b) * 1024 + colA;
        gxr = pk(__ldg(gpx), __ldg(gpx + 256));
    }

#pragma unroll 1
    for (int s = 0; s < TS; ++s) {
        const int cur = s & 1;
        const int nxt = cur ^ 1;

        if (s + 1 < TS) {
            const float* gpx = g_gx + ((size_t)(TS - 2 - s) * 64 + gb0 + b) * 1024 + colA;
            gxn = pk(__ldg(gpx), __ldg(gpx + 256));
        }

        ull v[32];
        // chunk 0: OWN rank from smem — gated only by the producer bar
        {
            float4 h4 = *(const float4*)&hsm[cur][lane][0];
            ull hd0 = dup2(h4.x), hd1 = dup2(h4.y), hd2 = dup2(h4.z), hd3 = dup2(h4.w);
#pragma unroll
            for (int cpi = 0; cpi < 8; ++cpi) {
                v[cpi * 4 + 0] = mul2(hd0, wreg[0][cpi]);
                v[cpi * 4 + 1] = mul2(hd1, wreg[0][cpi]);
                v[cpi * 4 + 2] = mul2(hd2, wreg[0][cpi]);
                v[cpi * 4 + 3] = mul2(hd3, wreg[0][cpi]);
            }
        }

        // per-warp wait: lanes 0..7 poll remote flags (own rank skipped)
        if (s) {
            if (lane < 8 && lane != r) {
                const unsigned tgt = (unsigned)s;
                const unsigned* fp = &g_flag[layer][grp][lane][0];
#pragma unroll 1
                while (ldacq(fp) < tgt) { }
            }
            __syncwarp();
        }

        // chunks 1..7: back-to-back ldcgs (MLP=7), then fma blocks
#pragma unroll
        for (int i = 1; i < 8; ++i) {
            float4 h4 = make_float4(0.f, 0.f, 0.f, 0.f);
            if (s) h4 = __ldcg((const float4*)&g_hx[cur][grp][((r + i) & 7) * 32 + lane][0]);
            ull hd0 = dup2(h4.x), hd1 = dup2(h4.y), hd2 = dup2(h4.z), hd3 = dup2(h4.w);
#pragma unroll
            for (int cpi = 0; cpi < 8; ++cpi) {
                v[cpi * 4 + 0] = fma2(hd0, wreg[i][cpi], v[cpi * 4 + 0]);
                v[cpi * 4 + 1] = fma2(hd1, wreg[i][cpi], v[cpi * 4 + 1]);
                v[cpi * 4 + 2] = fma2(hd2, wreg[i][cpi], v[cpi * 4 + 2]);
                v[cpi * 4 + 3] = fma2(hd3, wreg[i][cpi], v[cpi * 4 + 3]);
            }
        }

        // reduce-scatter butterfly: lane l ends holding (cp=l>>2, b=l&3)
#pragma unroll
        for (int t = 0; t < 5; ++t) {
            const int mybit = (lane >> t) & 1;
            const int n = 32 >> t;
#pragma unroll
            for (int i = 0; i < 16; ++i) {
                if (i < (n >> 1)) {
                    ull lo = v[2 * i], hi = v[2 * i + 1];
                    ull send = mybit ? lo : hi;
                    ull recv = __shfl_xor_sync(0xffffffffu, send, 1 << t);
                    v[i] = add2(mybit ? hi : lo, recv);
                }
            }
        }

        // epilogue
        float h1 = 0.f;
        {
            float p0, p1;
            upk(add2(v[0], gxr), p0, p1);
            float a0 = sigf(p0);
            float a1 = gp ? tanhap(p1) : sigf(p1);
            ull other = __shfl_xor_sync(0xffffffffu, pk(a0, a1), 4);
            if (gp == 0) {
                float so, tg; upk(other, so, tg);
                cst = a0 * cst + a1 * tg;
                h1 = so * tanhap(cst);
            }
        }
        gxr = gxn;

        // coalesced h publish: gather unit u's 4 batch values into lane 8u
        {
            float4 hv;
            const int base = lane & 24;
            hv.x = __shfl_sync(0xffffffffu, h1, base);
            hv.y = __shfl_sync(0xffffffffu, h1, base + 1);
            hv.z = __shfl_sync(0xffffffffu, h1, base + 2);
            hv.w = __shfl_sync(0xffffffffu, h1, base + 3);
            if ((lane & 7) == 0 && s < TS - 1) {
                const int row = r * 32 + w * 4 + (lane >> 3);
                *(float4*)&g_hx[nxt][grp][row][0] = hv;            // 1 STG.128
                *(float4*)&hsm[nxt][w * 4 + (lane >> 3)][0] = hv;  // 1 STS.128
            }
        }

        __syncthreads();              // h stores happen-before the release
        if (s < TS - 1 && tid == 0)
            asm volatile("st.release.gpu.global.u32 [%0], %1;"
                         :: "l"(myflag), "r"((unsigned)(s + 1)) : "memory");

        // outputs AFTER the publish — off the critical chain
        if (gp == 0) {
            yout[((size_t)s * 64 + gb0 + b) * 256 + jj] = h1;
            if (s == TS - 1) {
                size_t hi_ = (size_t)(gb0 + b) * 256 + jj;
                hn[hi_] = h1; cn[hi_] = cst;
            }
        }
    }

    // reset flags for the next graph replay (deterministic launches)
    __syncthreads();
    if (tid == 0) {
        asm volatile("red.release.gpu.global.add.u32 [%0], 1;" :: "l"(fin) : "memory");
        if (r == 0) {
#pragma unroll 1
            while (ldacq(fin) < 8u) { }
#pragma unroll
            for (int d = 0; d < 8; ++d)
                asm volatile("st.global.u32 [%0], %1;"
                             :: "l"(&g_flag[layer][grp][d][0]), "r"(0u) : "memory");
            asm volatile("st.global.u32 [%0], %1;" :: "l"(fin), "r"(0u) : "memory");
        }
    }
}

extern "C" void kernel_launch(void* const* d_in, const int* in_sizes, int n_in,
                              void* d_out, int out_size)
{
    const float* x    = (const float*)d_in[0];
    const float* wih0 = (const float*)d_in[1];
    const float* whh0 = (const float*)d_in[2];
    const float* b0   = (const float*)d_in[3];
    const float* wih1 = (const float*)d_in[4];
    const float* whh1 = (const float*)d_in[5];
    const float* b1   = (const float*)d_in[6];
    float* out = (float*)d_out;

    dim3 gg(8, 1024);
    gemm_k<<<gg, 256>>>(x, wih0, b0, 128, 0);
    recur_k<<<128, 256>>>(whh0, out, 0);
    gemm_k<<<gg, 256>>>(x, wih1, b1, 256, 1);
    recur_k<<<128, 256>>>(whh1, out, 1);
}